// round 10
// baseline (speedup 1.0000x reference)
#include <cuda_runtime.h>
#include <cuda_fp16.h>
#include <math.h>
#include <stdint.h>

// Problem constants
#define BSZ    32
#define NSEQ   256
#define HDIM   512
#define NHEADS 8
#define DHEAD  64
#define FDIM   2048
#define LNUM   8
#define MROWS  (BSZ * NSEQ)   // 8192
#define NBH    (BSZ * NHEADS) // 256

// ---------------------------------------------------------------------------
// Scratch (static device globals; no runtime allocation allowed)
// Activations fp16; residual stream fp32 in d_out.
// ---------------------------------------------------------------------------
__device__ __half g_y  [MROWS * HDIM];
__device__ __half g_q  [MROWS * HDIM];
__device__ __half g_k  [MROWS * HDIM];
__device__ __half g_v  [MROWS * HDIM];
__device__ __half g_ctx[MROWS * HDIM];
__device__ __half g_ffn[MROWS * FDIM];
// Transposed weights: Wt[n][k] = half(W[k][n])
__device__ __half g_wqt[LNUM * HDIM * HDIM];
__device__ __half g_wkt[LNUM * HDIM * HDIM];
__device__ __half g_wvt[LNUM * HDIM * HDIM];
__device__ __half g_wot[LNUM * HDIM * HDIM];
__device__ __half g_w1t[LNUM * HDIM * FDIM];
__device__ __half g_w2t[LNUM * FDIM * HDIM];

// ---------------------------------------------------------------------------
// Helpers
// ---------------------------------------------------------------------------
__device__ __forceinline__ uint32_t smem_u32(const void* p) {
    uint32_t a;
    asm("{ .reg .u64 t; cvta.to.shared.u64 t, %1; cvt.u32.u64 %0, t; }"
        : "=r"(a) : "l"(p));
    return a;
}

__device__ __forceinline__ void cp_async16(void* dst, const void* src) {
    uint32_t d;
    asm("{ .reg .u64 t; cvta.to.shared.u64 t, %1; cvt.u32.u64 %0, t; }"
        : "=r"(d) : "l"(dst));
    asm volatile("cp.async.cg.shared.global [%0], [%1], 16;" :: "r"(d), "l"(src));
}

#define CP_COMMIT() asm volatile("cp.async.commit_group;" ::: "memory")
#define CP_WAIT(n)  asm volatile("cp.async.wait_group %0;" :: "n"(n) : "memory")

__device__ __forceinline__ void mma_f16(float* d, const uint32_t* a, const uint32_t* b) {
    asm volatile(
        "mma.sync.aligned.m16n8k16.row.col.f32.f16.f16.f32 "
        "{%0,%1,%2,%3}, {%4,%5,%6,%7}, {%8,%9}, {%0,%1,%2,%3};"
        : "+f"(d[0]), "+f"(d[1]), "+f"(d[2]), "+f"(d[3])
        : "r"(a[0]), "r"(a[1]), "r"(a[2]), "r"(a[3]), "r"(b[0]), "r"(b[1]));
}

__device__ __forceinline__ void ldsm_x4(uint32_t& r0, uint32_t& r1,
                                        uint32_t& r2, uint32_t& r3, uint32_t addr) {
    asm volatile("ldmatrix.sync.aligned.m8n8.x4.shared.b16 {%0,%1,%2,%3}, [%4];"
        : "=r"(r0), "=r"(r1), "=r"(r2), "=r"(r3) : "r"(addr));
}

__device__ __forceinline__ void ldsm_x4_t(uint32_t& r0, uint32_t& r1,
                                          uint32_t& r2, uint32_t& r3, uint32_t addr) {
    asm volatile("ldmatrix.sync.aligned.m8n8.x4.trans.shared.b16 {%0,%1,%2,%3}, [%4];"
        : "=r"(r0), "=r"(r1), "=r"(r2), "=r"(r3) : "r"(addr));
}

// ---------------------------------------------------------------------------
// fp16 tile loader: 128 rows x 64 halves (128 B/row), swizzled 16B chunks:
// chunk ck of row r lands at r*128 + ((ck ^ (r&7)) * 16)
// ---------------------------------------------------------------------------
__device__ __forceinline__ void load_tile128h(const __half* __restrict__ base, int lda,
                                              int c, char* sdst, int tid) {
    const __half* p = base + c * 64;
    #pragma unroll
    for (int i = 0; i < 8; i++) {
        const int id  = tid + i * 128;
        const int row = id >> 3;
        const int ck  = id & 7;
        const int off = row * 128 + ((ck ^ (row & 7)) * 16);
        cp_async16(sdst + off, p + (size_t)row * lda + ck * 8);
    }
}

// ---------------------------------------------------------------------------
// GEMM core: 128x128 tile, BK=64 halves, 128 threads (4 warps 2x2, 64x64),
// 3-stage cp.async pipeline, ldmatrix fragment loads.
// ---------------------------------------------------------------------------
#define TILE_B    16384                 // 128 x 64 halves
#define STAGE_B   32768
#define GSMEM3    (3 * STAGE_B)         // 98304

__device__ __forceinline__ void gemm_main_h(const __half* __restrict__ A, int lda,
                                            const __half* __restrict__ B, int ldb,
                                            int K, char* smem, int tid,
                                            float (&d)[4][8][4]) {
    const int warp   = tid >> 5;
    const int lane   = tid & 31;
    const int warp_m = (warp >> 1) * 64;
    const int warp_n = (warp & 1) * 64;
    const uint32_t su = smem_u32(smem);

    const int rsw = lane & 7;
    const int hbA = lane >> 4;
    const int hbB = (lane >> 3) & 1;
    uint32_t rowA[4], rowB[4];
    #pragma unroll
    for (int mt = 0; mt < 4; mt++)
        rowA[mt] = (uint32_t)((warp_m + mt * 16 + (lane & 15)) * 128);
    #pragma unroll
    for (int p = 0; p < 4; p++)
        rowB[p] = (uint32_t)((warp_n + p * 16 + (lane & 7) + ((lane >> 4) * 8)) * 128);

    #pragma unroll
    for (int mt = 0; mt < 4; mt++)
        #pragma unroll
        for (int nt = 0; nt < 8; nt++)
            #pragma unroll
            for (int j = 0; j < 4; j++) d[mt][nt][j] = 0.0f;

    const int nch = K / 64;
    load_tile128h(A, lda, 0, smem, tid);
    load_tile128h(B, ldb, 0, smem + TILE_B, tid);
    CP_COMMIT();
    load_tile128h(A, lda, 1, smem + STAGE_B, tid);
    load_tile128h(B, ldb, 1, smem + STAGE_B + TILE_B, tid);
    CP_COMMIT();

    for (int c = 0; c < nch; c++) {
        if (c + 1 < nch) CP_WAIT(1);
        else             CP_WAIT(0);
        __syncthreads();

        if (c + 2 < nch) {
            char* st = smem + ((c + 2) % 3) * STAGE_B;
            load_tile128h(A, lda, c + 2, st, tid);
            load_tile128h(B, ldb, c + 2, st + TILE_B, tid);
            CP_COMMIT();
        }

        const uint32_t sA = su + (uint32_t)((c % 3) * STAGE_B);
        const uint32_t sB = sA + TILE_B;

        #pragma unroll
        for (int ks = 0; ks < 4; ks++) {
            const uint32_t offA = (uint32_t)(((((ks << 1) | hbA) ^ rsw)) << 4);
            const uint32_t offB = (uint32_t)(((((ks << 1) | hbB) ^ rsw)) << 4);

            uint32_t a[4][4];
            #pragma unroll
            for (int mt = 0; mt < 4; mt++)
                ldsm_x4(a[mt][0], a[mt][1], a[mt][2], a[mt][3],
                        sA + rowA[mt] + offA);
            uint32_t b[8][2];
            #pragma unroll
            for (int p = 0; p < 4; p++)
                ldsm_x4(b[2 * p][0], b[2 * p][1], b[2 * p + 1][0], b[2 * p + 1][1],
                        sB + rowB[p] + offB);
            #pragma unroll
            for (int mt = 0; mt < 4; mt++)
                #pragma unroll
                for (int nt = 0; nt < 8; nt++)
                    mma_f16(d[mt][nt], a[mt], b[nt]);
        }
    }
}

// ---------------------------------------------------------------------------
// Generic GEMM kernels (fp16 in, weights pre-transposed)
//   EPI 2: half(gelu(acc + bias)) -> half C   EPI 3: fp32 C += acc + bias
// ---------------------------------------------------------------------------
template <int EPI>
__global__ __launch_bounds__(128, 2)
void tgemm_kernel(const __half* __restrict__ A, const __half* __restrict__ Bt,
                  const float* __restrict__ bias, void* __restrict__ Cv,
                  int Ncols, int K) {
    extern __shared__ __align__(16) char smem[];
    const int tid  = threadIdx.x;
    const int warp = tid >> 5;
    const int lane = tid & 31;
    const int m0 = blockIdx.y * 128;
    const int n0 = blockIdx.x * 128;

    float d[4][8][4];
    gemm_main_h(A + (size_t)m0 * K, K, Bt + (size_t)n0 * K, K, K, smem, tid, d);

    const int warp_m = (warp >> 1) * 64;
    const int warp_n = (warp & 1) * 64;
    const int row = lane >> 2, col = lane & 3;

    #pragma unroll
    for (int nt = 0; nt < 8; nt++) {
        const int nb = n0 + warp_n + nt * 8 + col * 2;
        const float2 bv = *(const float2*)(bias + nb);
        #pragma unroll
        for (int mt = 0; mt < 4; mt++) {
            const int m1 = m0 + warp_m + mt * 16 + row;
            #pragma unroll
            for (int half_i = 0; half_i < 2; half_i++) {
                const int mr = m1 + half_i * 8;
                float v0 = d[mt][nt][half_i * 2 + 0] + bv.x;
                float v1 = d[mt][nt][half_i * 2 + 1] + bv.y;
                if (EPI == 2) {
                    v0 = 0.5f * v0 * (1.0f + erff(v0 * 0.70710678118654752f));
                    v1 = 0.5f * v1 * (1.0f + erff(v1 * 0.70710678118654752f));
                    __half* crow = (__half*)Cv + (size_t)mr * Ncols + nb;
                    *(__half2*)crow = __floats2half2_rn(v0, v1);
                } else {
                    float* crow = (float*)Cv + (size_t)mr * Ncols + nb;
                    const float2 old = *(const float2*)crow;
                    *(float2*)crow = make_float2(v0 + old.x, v1 + old.y);
                }
            }
        }
    }
}

// ---------------------------------------------------------------------------
// Fused QKV projection: grid.x = 12 -> (sel = x>>2) in {q,k,v}, n0 = (x&3)*128
// ---------------------------------------------------------------------------
__global__ __launch_bounds__(128, 2)
void qkv_kernel(const __half* __restrict__ A,
                const __half* __restrict__ wqt, const __half* __restrict__ wkt,
                const __half* __restrict__ wvt,
                const float* __restrict__ bq, const float* __restrict__ bk,
                const float* __restrict__ bv,
                __half* __restrict__ q, __half* __restrict__ k, __half* __restrict__ v) {
    extern __shared__ __align__(16) char smem[];
    const int tid  = threadIdx.x;
    const int warp = tid >> 5;
    const int lane = tid & 31;
    const int sel = blockIdx.x >> 2;
    const int n0  = (blockIdx.x & 3) * 128;
    const int m0  = blockIdx.y * 128;

    const __half* Bt  = (sel == 0) ? wqt : (sel == 1) ? wkt : wvt;
    const float* bias = (sel == 0) ? bq  : (sel == 1) ? bk  : bv;
    __half*      C    = (sel == 0) ? q   : (sel == 1) ? k   : v;
    const float scale = (sel == 0) ? 0.125f : 1.0f;

    float d[4][8][4];
    gemm_main_h(A + (size_t)m0 * HDIM, HDIM, Bt + (size_t)n0 * HDIM, HDIM, HDIM,
                smem, tid, d);

    const int warp_m = (warp >> 1) * 64;
    const int warp_n = (warp & 1) * 64;
    const int row = lane >> 2, col = lane & 3;

    #pragma unroll
    for (int nt = 0; nt < 8; nt++) {
        const int nb = n0 + warp_n + nt * 8 + col * 2;
        const float2 bvv = *(const float2*)(bias + nb);
        #pragma unroll
        for (int mt = 0; mt < 4; mt++) {
            const int m1 = m0 + warp_m + mt * 16 + row;
            #pragma unroll
            for (int half_i = 0; half_i < 2; half_i++) {
                __half* crow = C + (size_t)(m1 + half_i * 8) * HDIM + nb;
                const float v0 = (d[mt][nt][half_i * 2 + 0] + bvv.x) * scale;
                const float v1 = (d[mt][nt][half_i * 2 + 1] + bvv.y) * scale;
                *(__half2*)crow = __floats2half2_rn(v0, v1);
            }
        }
    }
}

// ---------------------------------------------------------------------------
// Fused flash attention (fp16): ctx = softmax(Q·K^T + bias) · V
// Grid (2 q-tiles, 256 bh), 256 threads (8 warps x 16 q-rows).
// V loaded DIRECTLY from g_v; transposed fragments via ldmatrix.trans.
// smem: [0,16K) Q (then per-warp P); [16K,32K) stage0 (K 8K | V 8K); [32K,48K) stage1
// ---------------------------------------------------------------------------
#define FA_STAGE 16384
#define FA_SMEM  (16384 + 2 * FA_STAGE)   // 49152

__device__ __forceinline__ void load_kv_h(const __half* __restrict__ Kb,
                                          const __half* __restrict__ Vb,
                                          int j0, char* st, int tid) {
    char* Ks = st;
    char* Vs = st + 8192;
    #pragma unroll
    for (int i = 0; i < 2; i++) {
        const int id = tid + i * 256;     // 0..511
        const int r  = id >> 3;           // 0..63 (key row)
        const int ck = id & 7;
        const int off = r * 128 + ((ck ^ (r & 7)) * 16);
        cp_async16(Ks + off, Kb + (size_t)(j0 + r) * HDIM + ck * 8);
        cp_async16(Vs + off, Vb + (size_t)(j0 + r) * HDIM + ck * 8);
    }
}

__global__ __launch_bounds__(256, 2)
void fattn_kernel(const __half* __restrict__ q, const __half* __restrict__ k,
                  const __half* __restrict__ v, const float* __restrict__ attn_bias,
                  __half* __restrict__ ctx) {
    extern __shared__ __align__(16) char smem[];
    char* QP    = smem;            // 128 rows x 128 B  (Q, later per-warp P)
    char* stage = smem + 16384;

    const int tid  = threadIdx.x;
    const int warp = tid >> 5;
    const int lane = tid & 31;
    const int row  = lane >> 2;
    const int col  = lane & 3;
    const int bh = blockIdx.y;
    const int b  = bh >> 3, h = bh & 7;
    const int m0 = blockIdx.x * 128;

    const __half* Qb = q + (size_t)b * NSEQ * HDIM + (size_t)m0 * HDIM + h * DHEAD;
    const __half* Kb = k + (size_t)b * NSEQ * HDIM + h * DHEAD;
    const __half* Vb = v + (size_t)b * NSEQ * HDIM + h * DHEAD;

    // Stage Q: 128 rows x 64 halves, swizzled
    #pragma unroll
    for (int i = 0; i < 4; i++) {
        const int id = tid + i * 256;     // 0..1023
        const int r  = id >> 3;           // 0..127
        const int ck = id & 7;
        const int off = r * 128 + ((ck ^ (r & 7)) * 16);
        cp_async16(QP + off, Qb + (size_t)r * HDIM + ck * 8);
    }
    CP_COMMIT();
    load_kv_h(Kb, Vb, 0, stage, tid);
    CP_COMMIT();

    const uint32_t QPu  = smem_u32(QP);
    const uint32_t stgu = smem_u32(stage);

    const int rsw = lane & 7;
    const int hbA = lane >> 4;           // a-operand half-select
    const int hbB = (lane >> 3) & 1;     // b-operand (K) chunk half-select
    const uint32_t rowQ = (uint32_t)((warp * 16 + (lane & 15)) * 128);
    uint32_t rowK[4];
    #pragma unroll
    for (int p = 0; p < 4; p++)
        rowK[p] = (uint32_t)((p * 16 + (lane & 7) + ((lane >> 4) * 8)) * 128);
    const uint32_t rowV = (uint32_t)(((lane & 7) + 8 * ((lane >> 3) & 1)) * 128);
    const int hbV = lane >> 4;
    uint32_t offV[4];
    #pragma unroll
    for (int p = 0; p < 4; p++)
        offV[p] = (uint32_t)(((((p << 1) | hbV) ^ rsw)) << 4);

    // Wait for Q (KV0 still in flight), extract Q fragments via ldmatrix
    CP_WAIT(1);
    __syncthreads();
    uint32_t aq[4][4];
    #pragma unroll
    for (int ks = 0; ks < 4; ks++) {
        const uint32_t offA = (uint32_t)(((((ks << 1) | hbA) ^ rsw)) << 4);
        ldsm_x4(aq[ks][0], aq[ks][1], aq[ks][2], aq[ks][3], QPu + rowQ + offA);
    }
    __syncthreads();   // Q region now reusable as P buffer

    float m0r = -1e30f, m1r = -1e30f, l0 = 0.0f, l1 = 0.0f;
    float cacc[8][4];
    #pragma unroll
    for (int nt = 0; nt < 8; nt++)
        #pragma unroll
        for (int j = 0; j < 4; j++) cacc[nt][j] = 0.0f;

    const float* bias_b = attn_bias + (size_t)bh * NSEQ * NSEQ
                        + (size_t)(m0 + warp * 16 + row) * NSEQ;
    char* Pw = QP + warp * 2048;                 // per-warp 16 rows x 128 B
    const uint32_t Pwu  = QPu + (uint32_t)(warp * 2048);
    const uint32_t rowP = (uint32_t)((lane & 15) * 128);

    for (int c = 0; c < 4; c++) {
        CP_WAIT(0);
        __syncthreads();
        if (c < 3) {
            load_kv_h(Kb, Vb, (c + 1) * 64, stage + ((c + 1) & 1) * FA_STAGE, tid);
            CP_COMMIT();
        }

        const uint32_t sK = stgu + (uint32_t)((c & 1) * FA_STAGE);
        const uint32_t sV = sK + 8192;

        // S = Q · K^T over this 64-key chunk
        float s[8][4];
        #pragma unroll
        for (int nt = 0; nt < 8; nt++)
            #pragma unroll
            for (int j = 0; j < 4; j++) s[nt][j] = 0.0f;

        #pragma unroll
        for (int ks = 0; ks < 4; ks++) {
            const uint32_t offB = (uint32_t)(((((ks << 1) | hbB) ^ rsw)) << 4);
            uint32_t bfr[8][2];
            #pragma unroll
            for (int p = 0; p < 4; p++)
                ldsm_x4(bfr[2 * p][0], bfr[2 * p][1],
                        bfr[2 * p + 1][0], bfr[2 * p + 1][1],
                        sK + rowK[p] + offB);
            #pragma unroll
            for (int nt = 0; nt < 8; nt++)
                mma_f16(s[nt], aq[ks], bfr[nt]);
        }

        // + bias, chunk row-max
        float mx0 = -1e30f, mx1 = -1e30f;
        #pragma unroll
        for (int nt = 0; nt < 8; nt++) {
            const float* bp = bias_b + c * 64 + nt * 8 + 2 * col;
            const float2 b0 = *(const float2*)bp;
            const float2 b1 = *(const float2*)(bp + 8 * NSEQ);
            s[nt][0] += b0.x; s[nt][1] += b0.y;
            s[nt][2] += b1.x; s[nt][3] += b1.y;
            mx0 = fmaxf(mx0, fmaxf(s[nt][0], s[nt][1]));
            mx1 = fmaxf(mx1, fmaxf(s[nt][2], s[nt][3]));
        }
        mx0 = fmaxf(mx0, __shfl_xor_sync(0xffffffffu, mx0, 1));
        mx0 = fmaxf(mx0, __shfl_xor_sync(0xffffffffu, mx0, 2));
        mx1 = fmaxf(mx1, __shfl_xor_sync(0xffffffffu, mx1, 1));
        mx1 = fmaxf(mx1, __shfl_xor_sync(0xffffffffu, mx1, 2));

        const float mn0 = fmaxf(m0r, mx0);
        const float mn1 = fmaxf(m1r, mx1);
        const float f0 = __expf(m0r - mn0);
        const float f1 = __expf(m1r - mn1);
        m0r = mn0; m1r = mn1;

        float sum0 = 0.0f, sum1 = 0.0f;
        #pragma unroll
        for (int nt = 0; nt < 8; nt++) {
            s[nt][0] = __expf(s[nt][0] - mn0);
            s[nt][1] = __expf(s[nt][1] - mn0);
            s[nt][2] = __expf(s[nt][2] - mn1);
            s[nt][3] = __expf(s[nt][3] - mn1);
            sum0 += s[nt][0] + s[nt][1];
            sum1 += s[nt][2] + s[nt][3];
        }
        l0 = l0 * f0 + sum0;
        l1 = l1 * f1 + sum1;
        #pragma unroll
        for (int nt = 0; nt < 8; nt++) {
            cacc[nt][0] *= f0; cacc[nt][1] *= f0;
            cacc[nt][2] *= f1; cacc[nt][3] *= f1;
        }

        // Store P tile (warp-private, 16 rows x 64 halves, swizzled)
        #pragma unroll
        for (int nt = 0; nt < 8; nt++) {
            const int swzp = ((nt ^ (row & 7)) * 16) + 4 * col;
            *(__half2*)(Pw + row * 128 + swzp) =
                __floats2half2_rn(s[nt][0], s[nt][1]);
            *(__half2*)(Pw + (row + 8) * 128 + swzp) =
                __floats2half2_rn(s[nt][2], s[nt][3]);
        }
        __syncwarp();

        // ctx += P · V  (V fragments transposed in LDSM unit)
        #pragma unroll
        for (int ks = 0; ks < 4; ks++) {
            const uint32_t offA = (uint32_t)(((((ks << 1) | hbA) ^ rsw)) << 4);
            uint32_t a[4];
            ldsm_x4(a[0], a[1], a[2], a[3], Pwu + rowP + offA);
            const uint32_t vbase = sV + (uint32_t)(ks * 2048) + rowV;
            uint32_t bfr[8][2];
            #pragma unroll
            for (int p = 0; p < 4; p++)
                ldsm_x4_t(bfr[2 * p][0], bfr[2 * p][1],
                          bfr[2 * p + 1][0], bfr[2 * p + 1][1],
                          vbase + offV[p]);
            #pragma unroll
            for (int nt = 0; nt < 8; nt++)
                mma_f16(cacc[nt], a, bfr[nt]);
        }
        __syncwarp();
    }

    // Final normalize + write ctx [b][q][h*64+d] (fp16)
    l0 += __shfl_xor_sync(0xffffffffu, l0, 1);
    l0 += __shfl_xor_sync(0xffffffffu, l0, 2);
    l1 += __shfl_xor_sync(0xffffffffu, l1, 1);
    l1 += __shfl_xor_sync(0xffffffffu, l1, 2);
    const float inv0 = 1.0f / l0;
    const float inv1 = 1.0f / l1;

    __half* Cb = ctx + (size_t)b * NSEQ * HDIM + h * DHEAD
               + (size_t)(m0 + warp * 16 + row) * HDIM;
    #pragma unroll
    for (int nt = 0; nt < 8; nt++) {
        const int nb = nt * 8 + 2 * col;
        *(__half2*)(Cb + nb) =
            __floats2half2_rn(cacc[nt][0] * inv0, cacc[nt][1] * inv0);
        *(__half2*)(Cb + 8 * HDIM + nb) =
            __floats2half2_rn(cacc[nt][2] * inv1, cacc[nt][3] * inv1);
    }
}

// ---------------------------------------------------------------------------
// Weight transpose + fp16 convert: dst[n][k] = half(src[k][n]) per layer
// ---------------------------------------------------------------------------
__global__ void transpose_kernel(const float* __restrict__ src,
                                 __half* __restrict__ dst, int R, int C) {
    __shared__ float t[32][33];
    const size_t lo = (size_t)blockIdx.z * R * C;
    const int c0 = blockIdx.x * 32, r0 = blockIdx.y * 32;
    #pragma unroll
    for (int i = 0; i < 32; i += 8)
        t[threadIdx.y + i][threadIdx.x] =
            src[lo + (size_t)(r0 + threadIdx.y + i) * C + c0 + threadIdx.x];
    __syncthreads();
    #pragma unroll
    for (int i = 0; i < 32; i += 8)
        dst[lo + (size_t)(c0 + threadIdx.y + i) * R + r0 + threadIdx.x] =
            __float2half_rn(t[threadIdx.x][threadIdx.y + i]);
}

// ---------------------------------------------------------------------------
// LayerNorm: one block (256 threads) per row of 512; exact two-pass, fp16 out
// ---------------------------------------------------------------------------
__global__ void ln_kernel(const float* __restrict__ x,
                          const float* __restrict__ gs,
                          const float* __restrict__ gb,
                          __half* __restrict__ y) {
    __shared__ float red[8];
    const int row = blockIdx.x;
    const int tid = threadIdx.x;
    const float* xr = x + (size_t)row * HDIM;

    float v0 = xr[tid];
    float v1 = xr[tid + 256];

    float s = v0 + v1;
    #pragma unroll
    for (int o = 16; o; o >>= 1) s += __shfl_xor_sync(0xffffffffu, s, o);
    if ((tid & 31) == 0) red[tid >> 5] = s;
    __syncthreads();
    if (tid < 8) {
        float t = red[tid];
        #pragma unroll
        for (int o = 4; o; o >>= 1) t += __shfl_xor_sync(0xffu, t, o);
        if (tid == 0) red[0] = t;
    }
    __syncthreads();
    const float mu = red[0] * (1.0f / HDIM);
    __syncthreads();

    const float d0 = v0 - mu, d1 = v1 - mu;
    float sq = d0 * d0 + d1 * d1;
    #pragma unroll
    for (int o = 16; o; o >>= 1) sq += __shfl_xor_sync(0xffffffffu, sq, o);
    if ((tid & 31) == 0) red[tid >> 5] = sq;
    __syncthreads();
    if (tid < 8) {
        float t = red[tid];
        #pragma unroll
        for (int o = 4; o; o >>= 1) t += __shfl_xor_sync(0xffu, t, o);
        if (tid == 0) red[0] = t;
    }
    __syncthreads();
    const float inv = rsqrtf(red[0] * (1.0f / HDIM) + 1e-5f);

    __half* yr = y + (size_t)row * HDIM;
    yr[tid]       = __float2half_rn(d0 * inv * gs[tid]       + gb[tid]);
    yr[tid + 256] = __float2half_rn(d1 * inv * gs[tid + 256] + gb[tid + 256]);
}

// ---------------------------------------------------------------------------
// Host launcher
// ---------------------------------------------------------------------------
extern "C" void kernel_launch(void* const* d_in, const int* in_sizes, int n_in,
                              void* d_out, int out_size) {
    const float* x_in      = (const float*)d_in[0];
    const float* attn_bias = (const float*)d_in[1];
    const float* ln1_s     = (const float*)d_in[2];
    const float* ln1_b     = (const float*)d_in[3];
    const float* wq        = (const float*)d_in[4];
    const float* bq        = (const float*)d_in[5];
    const float* wk        = (const float*)d_in[6];
    const float* bk        = (const float*)d_in[7];
    const float* wv        = (const float*)d_in[8];
    const float* bv        = (const float*)d_in[9];
    const float* wo        = (const float*)d_in[10];
    const float* bo        = (const float*)d_in[11];
    const float* ln2_s     = (const float*)d_in[12];
    const float* ln2_b     = (const float*)d_in[13];
    const float* w1        = (const float*)d_in[14];
    const float* b1        = (const float*)d_in[15];
    const float* w2        = (const float*)d_in[16];
    const float* b2        = (const float*)d_in[17];

    float* X = (float*)d_out;

    __half *yb, *qb, *kb, *vb, *cb, *fb;
    __half *wqt, *wkt, *wvt, *wot, *w1t, *w2t;
    cudaGetSymbolAddress((void**)&yb, g_y);
    cudaGetSymbolAddress((void**)&qb, g_q);
    cudaGetSymbolAddress((void**)&kb, g_k);
    cudaGetSymbolAddress((void**)&vb, g_v);
    cudaGetSymbolAddress((void**)&cb, g_ctx);
    cudaGetSymbolAddress((void**)&fb, g_ffn);
    cudaGetSymbolAddress((void**)&wqt, g_wqt);
    cudaGetSymbolAddress((void**)&wkt, g_wkt);
    cudaGetSymbolAddress((void**)&wvt, g_wvt);
    cudaGetSymbolAddress((void**)&wot, g_wot);
    cudaGetSymbolAddress((void**)&w1t, g_w1t);
    cudaGetSymbolAddress((void**)&w2t, g_w2t);

    cudaFuncSetAttribute(tgemm_kernel<2>,
                         cudaFuncAttributeMaxDynamicSharedMemorySize, GSMEM3);
    cudaFuncSetAttribute(tgemm_kernel<3>,
                         cudaFuncAttributeMaxDynamicSharedMemorySize, GSMEM3);
    cudaFuncSetAttribute(qkv_kernel,
                         cudaFuncAttributeMaxDynamicSharedMemorySize, GSMEM3);
    cudaFuncSetAttribute(fattn_kernel,
                         cudaFuncAttributeMaxDynamicSharedMemorySize, FA_SMEM);

    cudaMemcpyAsync(X, x_in, (size_t)MROWS * HDIM * sizeof(float),
                    cudaMemcpyDeviceToDevice);

    // One-time weight transposes (+ fp16 convert)
    {
        const dim3 tb(32, 8);
        const dim3 gHH(HDIM / 32, HDIM / 32, LNUM);
        const dim3 gHF(FDIM / 32, HDIM / 32, LNUM);
        const dim3 gFH(HDIM / 32, FDIM / 32, LNUM);
        transpose_kernel<<<gHH, tb>>>(wq, wqt, HDIM, HDIM);
        transpose_kernel<<<gHH, tb>>>(wk, wkt, HDIM, HDIM);
        transpose_kernel<<<gHH, tb>>>(wv, wvt, HDIM, HDIM);
        transpose_kernel<<<gHH, tb>>>(wo, wot, HDIM, HDIM);
        transpose_kernel<<<gHF, tb>>>(w1, w1t, HDIM, FDIM);
        transpose_kernel<<<gFH, tb>>>(w2, w2t, FDIM, HDIM);
    }

    const dim3 gB(256);
    const dim3 tG(128);
    const dim3 gQKV(12, MROWS / 128);            // (12, 64)
    const dim3 gProj(HDIM / 128, MROWS / 128);   // (4, 64)
    const dim3 gFfn1(FDIM / 128, MROWS / 128);   // (16, 64)
    const dim3 gFA(NSEQ / 128, NBH);             // (2, 256)

    for (int l = 0; l < LNUM; l++) {
        const __half* wqt_l = wqt + (size_t)l * HDIM * HDIM;
        const __half* wkt_l = wkt + (size_t)l * HDIM * HDIM;
        const __half* wvt_l = wvt + (size_t)l * HDIM * HDIM;
        const __half* wot_l = wot + (size_t)l * HDIM * HDIM;
        const __half* w1t_l = w1t + (size_t)l * HDIM * FDIM;
        const __half* w2t_l = w2t + (size_t)l * FDIM * HDIM;

        // --- attention block ---
        ln_kernel<<<MROWS, gB>>>(X, ln1_s + l * HDIM, ln1_b + l * HDIM, yb);
        qkv_kernel<<<gQKV, tG, GSMEM3>>>(yb, wqt_l, wkt_l, wvt_l,
                                         bq + l * HDIM, bk + l * HDIM, bv + l * HDIM,
                                         qb, kb, vb);
        fattn_kernel<<<gFA, gB, FA_SMEM>>>(qb, kb, vb, attn_bias, cb);
        tgemm_kernel<3><<<gProj, tG, GSMEM3>>>(cb, wot_l, bo + l * HDIM, X,
                                               HDIM, HDIM);

        // --- FFN block ---
        ln_kernel<<<MROWS, gB>>>(X, ln2_s + l * HDIM, ln2_b + l * HDIM, yb);
        tgemm_kernel<2><<<gFfn1, tG, GSMEM3>>>(yb, w1t_l, b1 + l * FDIM, fb,
                                               FDIM, HDIM);
        tgemm_kernel<3><<<gProj, tG, GSMEM3>>>(fb, w2t_l, b2 + l * HDIM, X,
                                               HDIM, FDIM);
    }
}

// round 11
// speedup vs baseline: 1.4098x; 1.4098x over previous
#include <cuda_runtime.h>
#include <cuda_fp16.h>
#include <math.h>
#include <stdint.h>

// Problem constants
#define BSZ    32
#define NSEQ   256
#define HDIM   512
#define NHEADS 8
#define DHEAD  64
#define FDIM   2048
#define LNUM   8
#define MROWS  (BSZ * NSEQ)   // 8192
#define NBH    (BSZ * NHEADS) // 256

// ---------------------------------------------------------------------------
// Scratch (static device globals; no runtime allocation allowed)
// Activations in fp16; residual stream stays fp32 in d_out.
// ---------------------------------------------------------------------------
__device__ __half g_y  [MROWS * HDIM];
__device__ __half g_q  [MROWS * HDIM];
__device__ __half g_k  [MROWS * HDIM];
__device__ __half g_v  [MROWS * HDIM];
__device__ __half g_ctx[MROWS * HDIM];
__device__ __half g_ffn[MROWS * FDIM];
__device__ __half g_vt [NBH * DHEAD * NSEQ];    // per-head transposed V
// Transposed weights: Wt[n][k] = half(W[k][n])
__device__ __half g_wqt[LNUM * HDIM * HDIM];
__device__ __half g_wkt[LNUM * HDIM * HDIM];
__device__ __half g_wvt[LNUM * HDIM * HDIM];
__device__ __half g_wot[LNUM * HDIM * HDIM];
__device__ __half g_w1t[LNUM * HDIM * FDIM];
__device__ __half g_w2t[LNUM * FDIM * HDIM];

// ---------------------------------------------------------------------------
// Helpers
// ---------------------------------------------------------------------------
__device__ __forceinline__ void cp_async16(void* dst, const void* src) {
    uint32_t d;
    asm("{ .reg .u64 t; cvta.to.shared.u64 t, %1; cvt.u32.u64 %0, t; }"
        : "=r"(d) : "l"(dst));
    asm volatile("cp.async.cg.shared.global [%0], [%1], 16;" :: "r"(d), "l"(src));
}

#define CP_COMMIT() asm volatile("cp.async.commit_group;" ::: "memory")
#define CP_WAIT(n)  asm volatile("cp.async.wait_group %0;" :: "n"(n) : "memory")

// fp16 MMA m16n8k16, fp32 accumulate
__device__ __forceinline__ void mma_f16(float* d, const uint32_t* a, const uint32_t* b) {
    asm volatile(
        "mma.sync.aligned.m16n8k16.row.col.f32.f16.f16.f32 "
        "{%0,%1,%2,%3}, {%4,%5,%6,%7}, {%8,%9}, {%0,%1,%2,%3};"
        : "+f"(d[0]), "+f"(d[1]), "+f"(d[2]), "+f"(d[3])
        : "r"(a[0]), "r"(a[1]), "r"(a[2]), "r"(a[3]), "r"(b[0]), "r"(b[1]));
}

// ---------------------------------------------------------------------------
// fp16 tile loader: 128 rows x 64 halves (128 B/row), swizzled 16B chunks:
// chunk ck of row r lands at r*128 + ((ck ^ (r&7)) * 16)
// ---------------------------------------------------------------------------
__device__ __forceinline__ void load_tile128h(const __half* __restrict__ base, int lda,
                                              int c, char* sdst, int tid) {
    const __half* p = base + c * 64;
    #pragma unroll
    for (int i = 0; i < 8; i++) {
        const int id  = tid + i * 128;
        const int row = id >> 3;
        const int ck  = id & 7;
        const int off = row * 128 + ((ck ^ (row & 7)) * 16);
        cp_async16(sdst + off, p + (size_t)row * lda + ck * 8);
    }
}

// ---------------------------------------------------------------------------
// GEMM core: 128x128 tile, BK=64 halves, 128 threads (4 warps 2x2, 64x64),
// 3-stage cp.async pipeline, single __syncthreads per chunk.
// ---------------------------------------------------------------------------
#define TILE_B    16384                 // 128 x 64 halves
#define STAGE_B   32768
#define GSMEM3    (3 * STAGE_B)         // 98304

__device__ __forceinline__ void gemm_main_h(const __half* __restrict__ A, int lda,
                                            const __half* __restrict__ B, int ldb,
                                            int K, char* smem, int tid,
                                            float (&d)[4][8][4]) {
    const int warp   = tid >> 5;
    const int lane   = tid & 31;
    const int warp_m = (warp >> 1) * 64;
    const int warp_n = (warp & 1) * 64;
    const int row    = lane >> 2;
    const int col    = lane & 3;

    #pragma unroll
    for (int mt = 0; mt < 4; mt++)
        #pragma unroll
        for (int nt = 0; nt < 8; nt++)
            #pragma unroll
            for (int j = 0; j < 4; j++) d[mt][nt][j] = 0.0f;

    const int nch = K / 64;
    load_tile128h(A, lda, 0, smem, tid);
    load_tile128h(B, ldb, 0, smem + TILE_B, tid);
    CP_COMMIT();
    load_tile128h(A, lda, 1, smem + STAGE_B, tid);
    load_tile128h(B, ldb, 1, smem + STAGE_B + TILE_B, tid);
    CP_COMMIT();

    for (int c = 0; c < nch; c++) {
        if (c + 1 < nch) CP_WAIT(1);
        else             CP_WAIT(0);
        __syncthreads();

        if (c + 2 < nch) {
            char* st = smem + ((c + 2) % 3) * STAGE_B;
            load_tile128h(A, lda, c + 2, st, tid);
            load_tile128h(B, ldb, c + 2, st + TILE_B, tid);
            CP_COMMIT();
        }

        const char* Asb = smem + (c % 3) * STAGE_B;
        const char* Bsb = Asb + TILE_B;

        #pragma unroll
        for (int ks = 0; ks < 4; ks++) {
            const int ck   = ks * 2;
            const int swz0 = ((ck ^ (row & 7)) * 16) + 4 * col;
            const int swz1 = (((ck + 1) ^ (row & 7)) * 16) + 4 * col;

            uint32_t a[4][4];
            #pragma unroll
            for (int mt = 0; mt < 4; mt++) {
                const char* ap0 = Asb + (warp_m + mt * 16 + row) * 128;
                const char* ap8 = ap0 + 8 * 128;
                a[mt][0] = *(const uint32_t*)(ap0 + swz0);
                a[mt][1] = *(const uint32_t*)(ap8 + swz0);
                a[mt][2] = *(const uint32_t*)(ap0 + swz1);
                a[mt][3] = *(const uint32_t*)(ap8 + swz1);
            }
            uint32_t b[8][2];
            #pragma unroll
            for (int nt = 0; nt < 8; nt++) {
                const char* bp = Bsb + (warp_n + nt * 8 + row) * 128;
                b[nt][0] = *(const uint32_t*)(bp + swz0);
                b[nt][1] = *(const uint32_t*)(bp + swz1);
            }
            #pragma unroll
            for (int mt = 0; mt < 4; mt++)
                #pragma unroll
                for (int nt = 0; nt < 8; nt++)
                    mma_f16(d[mt][nt], a[mt], b[nt]);
        }
    }
}

// ---------------------------------------------------------------------------
// Generic GEMM kernels (fp16 in, weights pre-transposed)
//   EPI 2: half(gelu(acc + bias)) -> half C   EPI 3: fp32 C += acc + bias
// ---------------------------------------------------------------------------
template <int EPI>
__global__ __launch_bounds__(128, 2)
void tgemm_kernel(const __half* __restrict__ A, const __half* __restrict__ Bt,
                  const float* __restrict__ bias, void* __restrict__ Cv,
                  int Ncols, int K) {
    extern __shared__ __align__(16) char smem[];
    const int tid  = threadIdx.x;
    const int warp = tid >> 5;
    const int lane = tid & 31;
    const int m0 = blockIdx.y * 128;
    const int n0 = blockIdx.x * 128;

    float d[4][8][4];
    gemm_main_h(A + (size_t)m0 * K, K, Bt + (size_t)n0 * K, K, K, smem, tid, d);

    const int warp_m = (warp >> 1) * 64;
    const int warp_n = (warp & 1) * 64;
    const int row = lane >> 2, col = lane & 3;

    #pragma unroll
    for (int nt = 0; nt < 8; nt++) {
        const int nb = n0 + warp_n + nt * 8 + col * 2;
        const float2 bv = *(const float2*)(bias + nb);
        #pragma unroll
        for (int mt = 0; mt < 4; mt++) {
            const int m1 = m0 + warp_m + mt * 16 + row;
            #pragma unroll
            for (int half_i = 0; half_i < 2; half_i++) {
                const int mr = m1 + half_i * 8;
                float v0 = d[mt][nt][half_i * 2 + 0] + bv.x;
                float v1 = d[mt][nt][half_i * 2 + 1] + bv.y;
                if (EPI == 2) {
                    v0 = 0.5f * v0 * (1.0f + erff(v0 * 0.70710678118654752f));
                    v1 = 0.5f * v1 * (1.0f + erff(v1 * 0.70710678118654752f));
                    __half* crow = (__half*)Cv + (size_t)mr * Ncols + nb;
                    *(__half2*)crow = __floats2half2_rn(v0, v1);
                } else {
                    float* crow = (float*)Cv + (size_t)mr * Ncols + nb;
                    const float2 old = *(const float2*)crow;
                    *(float2*)crow = make_float2(v0 + old.x, v1 + old.y);
                }
            }
        }
    }
}

// ---------------------------------------------------------------------------
// Fused QKV projection: grid.x = 12 -> (sel = x>>2) in {q,k,v}, n0 = (x&3)*128
// ---------------------------------------------------------------------------
__global__ __launch_bounds__(128, 2)
void qkv_kernel(const __half* __restrict__ A,
                const __half* __restrict__ wqt, const __half* __restrict__ wkt,
                const __half* __restrict__ wvt,
                const float* __restrict__ bq, const float* __restrict__ bk,
                const float* __restrict__ bv,
                __half* __restrict__ q, __half* __restrict__ k, __half* __restrict__ v) {
    extern __shared__ __align__(16) char smem[];
    const int tid  = threadIdx.x;
    const int warp = tid >> 5;
    const int lane = tid & 31;
    const int sel = blockIdx.x >> 2;
    const int n0  = (blockIdx.x & 3) * 128;
    const int m0  = blockIdx.y * 128;

    const __half* Bt  = (sel == 0) ? wqt : (sel == 1) ? wkt : wvt;
    const float* bias = (sel == 0) ? bq  : (sel == 1) ? bk  : bv;
    __half*      C    = (sel == 0) ? q   : (sel == 1) ? k   : v;
    const float scale = (sel == 0) ? 0.125f : 1.0f;

    float d[4][8][4];
    gemm_main_h(A + (size_t)m0 * HDIM, HDIM, Bt + (size_t)n0 * HDIM, HDIM, HDIM,
                smem, tid, d);

    const int warp_m = (warp >> 1) * 64;
    const int warp_n = (warp & 1) * 64;
    const int row = lane >> 2, col = lane & 3;

    #pragma unroll
    for (int nt = 0; nt < 8; nt++) {
        const int nb = n0 + warp_n + nt * 8 + col * 2;
        const float2 bvv = *(const float2*)(bias + nb);
        #pragma unroll
        for (int mt = 0; mt < 4; mt++) {
            const int m1 = m0 + warp_m + mt * 16 + row;
            #pragma unroll
            for (int half_i = 0; half_i < 2; half_i++) {
                __half* crow = C + (size_t)(m1 + half_i * 8) * HDIM + nb;
                const float v0 = (d[mt][nt][half_i * 2 + 0] + bvv.x) * scale;
                const float v1 = (d[mt][nt][half_i * 2 + 1] + bvv.y) * scale;
                *(__half2*)crow = __floats2half2_rn(v0, v1);
            }
        }
    }
}

// ---------------------------------------------------------------------------
// Per-head V transpose: vt[bh][d][j] = v[b][j][h*64+d] (fp16)
// ---------------------------------------------------------------------------
__global__ void vt_kernel(const __half* __restrict__ v, __half* __restrict__ vt) {
    __shared__ __half t[32][33];
    const int bh = blockIdx.z;
    const int b  = bh >> 3, h = bh & 7;
    const int j0 = blockIdx.x * 32;
    const int d0 = blockIdx.y * 32;
    const __half* src = v + (size_t)b * NSEQ * HDIM + h * DHEAD;
    __half* dst = vt + (size_t)bh * DHEAD * NSEQ;
    #pragma unroll
    for (int i = 0; i < 32; i += 8)
        t[threadIdx.y + i][threadIdx.x] =
            src[(size_t)(j0 + threadIdx.y + i) * HDIM + d0 + threadIdx.x];
    __syncthreads();
    #pragma unroll
    for (int i = 0; i < 32; i += 8)
        dst[(size_t)(d0 + threadIdx.y + i) * NSEQ + j0 + threadIdx.x] =
            t[threadIdx.x][threadIdx.y + i];
}

// ---------------------------------------------------------------------------
// Fused flash attention (fp16 operands): ctx = softmax(Q·K^T + bias) · V
// Grid (2 q-tiles, 256 bh), 256 threads (8 warps x 16 q-rows).
// smem: [0,16K) Q (then per-warp P); [16K,32K) stage0 (K 8K | V 8K); [32K,48K) stage1
// ---------------------------------------------------------------------------
#define FA_STAGE 16384
#define FA_SMEM  (16384 + 2 * FA_STAGE)   // 49152

__device__ __forceinline__ void load_kv_h(const __half* __restrict__ Kb,
                                          const __half* __restrict__ Vb,
                                          int j0, char* st, int tid) {
    char* Ks = st;
    char* Vs = st + 8192;
    #pragma unroll
    for (int i = 0; i < 2; i++) {
        const int id = tid + i * 256;     // 0..511
        const int r  = id >> 3;           // 0..63
        const int ck = id & 7;
        const int off = r * 128 + ((ck ^ (r & 7)) * 16);
        cp_async16(Ks + off, Kb + (size_t)(j0 + r) * HDIM + ck * 8);
        cp_async16(Vs + off, Vb + (size_t)r * NSEQ + j0 + ck * 8);
    }
}

__global__ __launch_bounds__(256, 2)
void fattn_kernel(const __half* __restrict__ q, const __half* __restrict__ k,
                  const __half* __restrict__ vt, const float* __restrict__ attn_bias,
                  __half* __restrict__ ctx) {
    extern __shared__ __align__(16) char smem[];
    char* QP    = smem;            // 128 rows x 128 B  (Q, later per-warp P)
    char* stage = smem + 16384;

    const int tid  = threadIdx.x;
    const int warp = tid >> 5;
    const int lane = tid & 31;
    const int row  = lane >> 2;
    const int col  = lane & 3;
    const int bh = blockIdx.y;
    const int b  = bh >> 3, h = bh & 7;
    const int m0 = blockIdx.x * 128;

    const __half* Qb = q  + (size_t)b * NSEQ * HDIM + (size_t)m0 * HDIM + h * DHEAD;
    const __half* Kb = k  + (size_t)b * NSEQ * HDIM + h * DHEAD;
    const __half* Vb = vt + (size_t)bh * DHEAD * NSEQ;

    // Stage Q: 128 rows x 64 halves, swizzled
    #pragma unroll
    for (int i = 0; i < 4; i++) {
        const int id = tid + i * 256;     // 0..1023
        const int r  = id >> 3;           // 0..127
        const int ck = id & 7;
        const int off = r * 128 + ((ck ^ (r & 7)) * 16);
        cp_async16(QP + off, Qb + (size_t)r * HDIM + ck * 8);
    }
    CP_COMMIT();
    load_kv_h(Kb, Vb, 0, stage, tid);
    CP_COMMIT();

    // Wait for Q (KV0 still in flight), extract Q fragments
    CP_WAIT(1);
    __syncthreads();
    uint32_t aq[4][4];
    #pragma unroll
    for (int ks = 0; ks < 4; ks++) {
        const int ck   = ks * 2;
        const int swz0 = ((ck ^ (row & 7)) * 16) + 4 * col;
        const int swz1 = (((ck + 1) ^ (row & 7)) * 16) + 4 * col;
        const char* ap0 = QP + (warp * 16 + row) * 128;
        const char* ap8 = ap0 + 8 * 128;
        aq[ks][0] = *(const uint32_t*)(ap0 + swz0);
        aq[ks][1] = *(const uint32_t*)(ap8 + swz0);
        aq[ks][2] = *(const uint32_t*)(ap0 + swz1);
        aq[ks][3] = *(const uint32_t*)(ap8 + swz1);
    }
    __syncthreads();   // Q region now reusable as P buffer

    float m0r = -1e30f, m1r = -1e30f, l0 = 0.0f, l1 = 0.0f;
    float cacc[8][4];
    #pragma unroll
    for (int nt = 0; nt < 8; nt++)
        #pragma unroll
        for (int j = 0; j < 4; j++) cacc[nt][j] = 0.0f;

    const float* bias_b = attn_bias + (size_t)bh * NSEQ * NSEQ
                        + (size_t)(m0 + warp * 16 + row) * NSEQ;
    char* Pw = QP + warp * 2048;   // per-warp 16 rows x 128 B

    for (int c = 0; c < 4; c++) {
        CP_WAIT(0);
        __syncthreads();
        if (c < 3) {
            load_kv_h(Kb, Vb, (c + 1) * 64, stage + ((c + 1) & 1) * FA_STAGE, tid);
            CP_COMMIT();
        }

        const char* Ksb = stage + (c & 1) * FA_STAGE;
        const char* Vsb = Ksb + 8192;

        // S = Q · K^T over this 64-key chunk
        float s[8][4];
        #pragma unroll
        for (int nt = 0; nt < 8; nt++)
            #pragma unroll
            for (int j = 0; j < 4; j++) s[nt][j] = 0.0f;

        #pragma unroll
        for (int ks = 0; ks < 4; ks++) {
            const int ck   = ks * 2;
            const int swz0 = ((ck ^ (row & 7)) * 16) + 4 * col;
            const int swz1 = (((ck + 1) ^ (row & 7)) * 16) + 4 * col;
            uint32_t bfr[8][2];
            #pragma unroll
            for (int nt = 0; nt < 8; nt++) {
                const char* bp = Ksb + (nt * 8 + row) * 128;
                bfr[nt][0] = *(const uint32_t*)(bp + swz0);
                bfr[nt][1] = *(const uint32_t*)(bp + swz1);
            }
            #pragma unroll
            for (int nt = 0; nt < 8; nt++)
                mma_f16(s[nt], aq[ks], bfr[nt]);
        }

        // + bias, chunk row-max
        float mx0 = -1e30f, mx1 = -1e30f;
        #pragma unroll
        for (int nt = 0; nt < 8; nt++) {
            const float* bp = bias_b + c * 64 + nt * 8 + 2 * col;
            const float2 b0 = *(const float2*)bp;
            const float2 b1 = *(const float2*)(bp + 8 * NSEQ);
            s[nt][0] += b0.x; s[nt][1] += b0.y;
            s[nt][2] += b1.x; s[nt][3] += b1.y;
            mx0 = fmaxf(mx0, fmaxf(s[nt][0], s[nt][1]));
            mx1 = fmaxf(mx1, fmaxf(s[nt][2], s[nt][3]));
        }
        mx0 = fmaxf(mx0, __shfl_xor_sync(0xffffffffu, mx0, 1));
        mx0 = fmaxf(mx0, __shfl_xor_sync(0xffffffffu, mx0, 2));
        mx1 = fmaxf(mx1, __shfl_xor_sync(0xffffffffu, mx1, 1));
        mx1 = fmaxf(mx1, __shfl_xor_sync(0xffffffffu, mx1, 2));

        const float mn0 = fmaxf(m0r, mx0);
        const float mn1 = fmaxf(m1r, mx1);
        const float f0 = __expf(m0r - mn0);
        const float f1 = __expf(m1r - mn1);
        m0r = mn0; m1r = mn1;

        float sum0 = 0.0f, sum1 = 0.0f;
        #pragma unroll
        for (int nt = 0; nt < 8; nt++) {
            s[nt][0] = __expf(s[nt][0] - mn0);
            s[nt][1] = __expf(s[nt][1] - mn0);
            s[nt][2] = __expf(s[nt][2] - mn1);
            s[nt][3] = __expf(s[nt][3] - mn1);
            sum0 += s[nt][0] + s[nt][1];
            sum1 += s[nt][2] + s[nt][3];
        }
        l0 = l0 * f0 + sum0;
        l1 = l1 * f1 + sum1;
        #pragma unroll
        for (int nt = 0; nt < 8; nt++) {
            cacc[nt][0] *= f0; cacc[nt][1] *= f0;
            cacc[nt][2] *= f1; cacc[nt][3] *= f1;
        }

        // Store P tile (warp-private, 16 rows x 64 halves, swizzled)
        #pragma unroll
        for (int nt = 0; nt < 8; nt++) {
            const int swzp = ((nt ^ (row & 7)) * 16) + 4 * col;
            *(__half2*)(Pw + row * 128 + swzp) =
                __floats2half2_rn(s[nt][0], s[nt][1]);
            *(__half2*)(Pw + (row + 8) * 128 + swzp) =
                __floats2half2_rn(s[nt][2], s[nt][3]);
        }
        __syncwarp();

        // ctx += P · V
        #pragma unroll
        for (int ks = 0; ks < 4; ks++) {
            const int ck   = ks * 2;
            const int swz0 = ((ck ^ (row & 7)) * 16) + 4 * col;
            const int swz1 = (((ck + 1) ^ (row & 7)) * 16) + 4 * col;
            const char* pp0 = Pw + row * 128;
            const char* pp8 = pp0 + 8 * 128;
            uint32_t a[4];
            a[0] = *(const uint32_t*)(pp0 + swz0);
            a[1] = *(const uint32_t*)(pp8 + swz0);
            a[2] = *(const uint32_t*)(pp0 + swz1);
            a[3] = *(const uint32_t*)(pp8 + swz1);
            uint32_t bfr[8][2];
            #pragma unroll
            for (int nt = 0; nt < 8; nt++) {
                const char* bp = Vsb + (nt * 8 + row) * 128;
                bfr[nt][0] = *(const uint32_t*)(bp + swz0);
                bfr[nt][1] = *(const uint32_t*)(bp + swz1);
            }
            #pragma unroll
            for (int nt = 0; nt < 8; nt++)
                mma_f16(cacc[nt], a, bfr[nt]);
        }
        __syncwarp();
    }

    // Final normalize + write ctx [b][q][h*64+d] (fp16)
    l0 += __shfl_xor_sync(0xffffffffu, l0, 1);
    l0 += __shfl_xor_sync(0xffffffffu, l0, 2);
    l1 += __shfl_xor_sync(0xffffffffu, l1, 1);
    l1 += __shfl_xor_sync(0xffffffffu, l1, 2);
    const float inv0 = 1.0f / l0;
    const float inv1 = 1.0f / l1;

    __half* Cb = ctx + (size_t)b * NSEQ * HDIM + h * DHEAD
               + (size_t)(m0 + warp * 16 + row) * HDIM;
    #pragma unroll
    for (int nt = 0; nt < 8; nt++) {
        const int nb = nt * 8 + 2 * col;
        *(__half2*)(Cb + nb) =
            __floats2half2_rn(cacc[nt][0] * inv0, cacc[nt][1] * inv0);
        *(__half2*)(Cb + 8 * HDIM + nb) =
            __floats2half2_rn(cacc[nt][2] * inv1, cacc[nt][3] * inv1);
    }
}

// ---------------------------------------------------------------------------
// Weight transpose + fp16 convert: dst[n][k] = half(src[k][n]) per layer
// ---------------------------------------------------------------------------
__global__ void transpose_kernel(const float* __restrict__ src,
                                 __half* __restrict__ dst, int R, int C) {
    __shared__ float t[32][33];
    const size_t lo = (size_t)blockIdx.z * R * C;
    const int c0 = blockIdx.x * 32, r0 = blockIdx.y * 32;
    #pragma unroll
    for (int i = 0; i < 32; i += 8)
        t[threadIdx.y + i][threadIdx.x] =
            src[lo + (size_t)(r0 + threadIdx.y + i) * C + c0 + threadIdx.x];
    __syncthreads();
    #pragma unroll
    for (int i = 0; i < 32; i += 8)
        dst[lo + (size_t)(c0 + threadIdx.y + i) * R + r0 + threadIdx.x] =
            __float2half_rn(t[threadIdx.x][threadIdx.y + i]);
}

// ---------------------------------------------------------------------------
// LayerNorm: warp-per-row (8 rows per 256-thread block), float4 loads,
// pure shfl reductions, no __syncthreads. fp16 out via uint2 stores.
// ---------------------------------------------------------------------------
__global__ __launch_bounds__(256)
void ln_kernel(const float* __restrict__ x,
               const float* __restrict__ gs,
               const float* __restrict__ gb,
               __half* __restrict__ y) {
    const int warp = threadIdx.x >> 5;
    const int lane = threadIdx.x & 31;
    const int row  = blockIdx.x * 8 + warp;

    const float4* xr = (const float4*)(x + (size_t)row * HDIM);
    float4 v[4];
    float s = 0.0f;
    #pragma unroll
    for (int j = 0; j < 4; j++) {
        v[j] = xr[j * 32 + lane];
        s += v[j].x + v[j].y + v[j].z + v[j].w;
    }
    #pragma unroll
    for (int o = 16; o; o >>= 1) s += __shfl_xor_sync(0xffffffffu, s, o);
    const float mu = s * (1.0f / HDIM);

    float sq = 0.0f;
    #pragma unroll
    for (int j = 0; j < 4; j++) {
        v[j].x -= mu; v[j].y -= mu; v[j].z -= mu; v[j].w -= mu;
        sq += v[j].x * v[j].x + v[j].y * v[j].y + v[j].z * v[j].z + v[j].w * v[j].w;
    }
    #pragma unroll
    for (int o = 16; o; o >>= 1) sq += __shfl_xor_sync(0xffffffffu, sq, o);
    const float inv = rsqrtf(sq * (1.0f / HDIM) + 1e-5f);

    const float4* gs4 = (const float4*)gs;
    const float4* gb4 = (const float4*)gb;
    uint2* yr = (uint2*)(y + (size_t)row * HDIM);
    #pragma unroll
    for (int j = 0; j < 4; j++) {
        const int idx = j * 32 + lane;
        const float4 g = gs4[idx];
        const float4 bb = gb4[idx];
        const __half2 lo = __floats2half2_rn(v[j].x * inv * g.x + bb.x,
                                             v[j].y * inv * g.y + bb.y);
        const __half2 hi = __floats2half2_rn(v[j].z * inv * g.z + bb.z,
                                             v[j].w * inv * g.w + bb.w);
        uint2 pk;
        pk.x = *(const uint32_t*)&lo;
        pk.y = *(const uint32_t*)&hi;
        yr[idx] = pk;
    }
}

// ---------------------------------------------------------------------------
// Host launcher
// ---------------------------------------------------------------------------
extern "C" void kernel_launch(void* const* d_in, const int* in_sizes, int n_in,
                              void* d_out, int out_size) {
    const float* x_in      = (const float*)d_in[0];
    const float* attn_bias = (const float*)d_in[1];
    const float* ln1_s     = (const float*)d_in[2];
    const float* ln1_b     = (const float*)d_in[3];
    const float* wq        = (const float*)d_in[4];
    const float* bq        = (const float*)d_in[5];
    const float* wk        = (const float*)d_in[6];
    const float* bk        = (const float*)d_in[7];
    const float* wv        = (const float*)d_in[8];
    const float* bv        = (const float*)d_in[9];
    const float* wo        = (const float*)d_in[10];
    const float* bo        = (const float*)d_in[11];
    const float* ln2_s     = (const float*)d_in[12];
    const float* ln2_b     = (const float*)d_in[13];
    const float* w1        = (const float*)d_in[14];
    const float* b1        = (const float*)d_in[15];
    const float* w2        = (const float*)d_in[16];
    const float* b2        = (const float*)d_in[17];

    float* X = (float*)d_out;

    __half *yb, *qb, *kb, *vb, *cb, *fb, *vt;
    __half *wqt, *wkt, *wvt, *wot, *w1t, *w2t;
    cudaGetSymbolAddress((void**)&yb, g_y);
    cudaGetSymbolAddress((void**)&qb, g_q);
    cudaGetSymbolAddress((void**)&kb, g_k);
    cudaGetSymbolAddress((void**)&vb, g_v);
    cudaGetSymbolAddress((void**)&cb, g_ctx);
    cudaGetSymbolAddress((void**)&fb, g_ffn);
    cudaGetSymbolAddress((void**)&vt, g_vt);
    cudaGetSymbolAddress((void**)&wqt, g_wqt);
    cudaGetSymbolAddress((void**)&wkt, g_wkt);
    cudaGetSymbolAddress((void**)&wvt, g_wvt);
    cudaGetSymbolAddress((void**)&wot, g_wot);
    cudaGetSymbolAddress((void**)&w1t, g_w1t);
    cudaGetSymbolAddress((void**)&w2t, g_w2t);

    cudaFuncSetAttribute(tgemm_kernel<2>,
                         cudaFuncAttributeMaxDynamicSharedMemorySize, GSMEM3);
    cudaFuncSetAttribute(tgemm_kernel<3>,
                         cudaFuncAttributeMaxDynamicSharedMemorySize, GSMEM3);
    cudaFuncSetAttribute(qkv_kernel,
                         cudaFuncAttributeMaxDynamicSharedMemorySize, GSMEM3);
    cudaFuncSetAttribute(fattn_kernel,
                         cudaFuncAttributeMaxDynamicSharedMemorySize, FA_SMEM);

    cudaMemcpyAsync(X, x_in, (size_t)MROWS * HDIM * sizeof(float),
                    cudaMemcpyDeviceToDevice);

    // One-time weight transposes (+ fp16 convert)
    {
        const dim3 tb(32, 8);
        const dim3 gHH(HDIM / 32, HDIM / 32, LNUM);
        const dim3 gHF(FDIM / 32, HDIM / 32, LNUM);
        const dim3 gFH(HDIM / 32, FDIM / 32, LNUM);
        transpose_kernel<<<gHH, tb>>>(wq, wqt, HDIM, HDIM);
        transpose_kernel<<<gHH, tb>>>(wk, wkt, HDIM, HDIM);
        transpose_kernel<<<gHH, tb>>>(wv, wvt, HDIM, HDIM);
        transpose_kernel<<<gHH, tb>>>(wo, wot, HDIM, HDIM);
        transpose_kernel<<<gHF, tb>>>(w1, w1t, HDIM, FDIM);
        transpose_kernel<<<gFH, tb>>>(w2, w2t, FDIM, HDIM);
    }

    const dim3 gB(256);
    const dim3 tG(128);
    const dim3 gLN(MROWS / 8);                   // 1024 blocks, warp-per-row
    const dim3 gQKV(12, MROWS / 128);            // (12, 64)
    const dim3 gProj(HDIM / 128, MROWS / 128);   // (4, 64)
    const dim3 gFfn1(FDIM / 128, MROWS / 128);   // (16, 64)
    const dim3 gFA(NSEQ / 128, NBH);             // (2, 256)
    const dim3 gVt(NSEQ / 32, DHEAD / 32, NBH);
    const dim3 tVt(32, 8);

    for (int l = 0; l < LNUM; l++) {
        const __half* wqt_l = wqt + (size_t)l * HDIM * HDIM;
        const __half* wkt_l = wkt + (size_t)l * HDIM * HDIM;
        const __half* wvt_l = wvt + (size_t)l * HDIM * HDIM;
        const __half* wot_l = wot + (size_t)l * HDIM * HDIM;
        const __half* w1t_l = w1t + (size_t)l * HDIM * FDIM;
        const __half* w2t_l = w2t + (size_t)l * FDIM * HDIM;

        // --- attention block ---
        ln_kernel<<<gLN, gB>>>(X, ln1_s + l * HDIM, ln1_b + l * HDIM, yb);
        qkv_kernel<<<gQKV, tG, GSMEM3>>>(yb, wqt_l, wkt_l, wvt_l,
                                         bq + l * HDIM, bk + l * HDIM, bv + l * HDIM,
                                         qb, kb, vb);
        vt_kernel<<<gVt, tVt>>>(vb, vt);
        fattn_kernel<<<gFA, gB, FA_SMEM>>>(qb, kb, vt, attn_bias, cb);
        tgemm_kernel<3><<<gProj, tG, GSMEM3>>>(cb, wot_l, bo + l * HDIM, X,
                                               HDIM, HDIM);

        // --- FFN block ---
        ln_kernel<<<gLN, gB>>>(X, ln2_s + l * HDIM, ln2_b + l * HDIM, yb);
        tgemm_kernel<2><<<gFfn1, tG, GSMEM3>>>(yb, w1t_l, b1 + l * FDIM, fb,
                                               FDIM, HDIM);
        tgemm_kernel<3><<<gProj, tG, GSMEM3>>>(fb, w2t_l, b2 + l * HDIM, X,
                                               HDIM, FDIM);
    }
}